// round 16
// baseline (speedup 1.0000x reference)
#include <cuda_runtime.h>

// Shared memory layout (float indices).
// SHC: double-buffered h, paired layout: addr(k,b) = buf*1024 + (k>>1)*16 + b*2 + (k&1)
//      k 0..63: h1 (layer0 out), k 64..127: h2 (layer1 out)
#define SHC   0        // 2048 floats (2 buffers)
#define SGT0  2048     // layer0 gates [256][8]
#define SGT1  4096     // layer1 gates [256][8]
#define SX    6144     // x tile [512][8]
#define SW    10240    // Whh1 tid-indexed: u64 [32 pairs][256 g] = 16384 floats
#define SMEM_FLOATS 26624   // 106496 bytes

typedef unsigned long long u64;

__device__ __forceinline__ float ftanh(float v) {
    float y;
    asm("tanh.approx.f32 %0, %1;" : "=f"(y) : "f"(v));
    return y;
}
__device__ __forceinline__ float fsig(float v) {
    return fmaf(ftanh(0.5f * v), 0.5f, 0.5f);
}
__device__ __forceinline__ u64 packf2(float lo, float hi) {
    u64 r;
    asm("mov.b64 %0, {%1, %2};" : "=l"(r)
        : "r"(__float_as_uint(lo)), "r"(__float_as_uint(hi)));
    return r;
}
__device__ __forceinline__ float2 unpackf2(u64 v) {
    unsigned int lo, hi;
    asm("mov.b64 {%0, %1}, %2;" : "=r"(lo), "=r"(hi) : "l"(v));
    return make_float2(__uint_as_float(lo), __uint_as_float(hi));
}
// d(lo,hi) += a(lo,hi) * b(lo,hi)   — packed dual-FMA (Blackwell f32x2)
__device__ __forceinline__ void ffma2(u64& d, u64 a, u64 b) {
    asm("fma.rn.f32x2 %0, %1, %2, %0;" : "+l"(d) : "l"(a), "l"(b));
}

__global__ void __launch_bounds__(512, 1)
lstm2_kernel(const float* __restrict__ x,
             const float* __restrict__ Wih0, const float* __restrict__ Whh0,
             const float* __restrict__ bih0, const float* __restrict__ bhh0,
             const float* __restrict__ Wih1, const float* __restrict__ Whh1,
             const float* __restrict__ bih1, const float* __restrict__ bhh1,
             const float* __restrict__ Wfc,  const float* __restrict__ bfc,
             float* __restrict__ out)
{
    extern __shared__ float sm[];
    u64* smW = (u64*)&sm[SW];
    const int tid = threadIdx.x;
    const int g   = tid & 255;           // gate row within this thread's group
    const int b0  = blockIdx.x * 8;      // batch base for this CTA

    // ---- init: x tile, zero h buffers, Whh1 -> smem (tid-indexed) ----
    for (int idx = tid; idx < 4096; idx += 512) {
        int t = idx >> 3, b = idx & 7;
        sm[SX + idx] = x[(b0 + b) * 512 + t];
    }
    for (int idx = tid; idx < 2048; idx += 512) sm[SHC + idx] = 0.f;
    if (tid >= 256) {
        const u64* ph = (const u64*)(Whh1 + g * 64);
        #pragma unroll
        for (int q = 0; q < 32; ++q) smW[q * 256 + g] = ph[q];
    }
    __syncthreads();

    const int bb = g & 7;        // batch lane for the update phase
    const int j0 = g >> 3;       // hidden-unit base (0..31); second unit = j0+32
    const int jB = j0 + 32;
    const int hs1a = (j0 >> 1) * 16 + bb * 2 + (j0 & 1);         // h1 slot unit j0
    const int hs1b = (jB >> 1) * 16 + bb * 2 + (jB & 1);         // h1 slot unit j0+32
    const int hs2a = 512 + hs1a;                                  // h2 slots
    const int hs2b = 512 + hs1b;

    if (tid < 256) {
        // =============== GROUP A: layer-0 gates + layer-0 update ===============
        const float wx_g    = Wih0[g];                   // [4H, I=1]
        const float bias0_g = bih0[g] + bhh0[g];
        u64 w0p[32];                                     // Whh0 row g (k-pair packed)
        {
            const u64* p0 = (const u64*)(Whh0 + g * 64);
            #pragma unroll
            for (int q = 0; q < 32; ++q) w0p[q] = p0[q];
        }
        float c0a = 0.f, c0b = 0.f;                      // cell state, units j0 / j0+32

        for (int s = 0; s <= 512; ++s) {
            const float* hbase = &sm[SHC + (s & 1) * 1024];
            float*       hdst  = &sm[SHC + ((s + 1) & 1) * 1024];
            if (s < 512) {
                const float4* xr = (const float4*)&sm[SX + s * 8];
                float4 xa = xr[0], xb = xr[1];
                u64 a0 = packf2(fmaf(wx_g, xa.x, bias0_g), 0.f);
                u64 a1 = packf2(fmaf(wx_g, xa.y, bias0_g), 0.f);
                u64 a2 = packf2(fmaf(wx_g, xa.z, bias0_g), 0.f);
                u64 a3 = packf2(fmaf(wx_g, xa.w, bias0_g), 0.f);
                u64 a4 = packf2(fmaf(wx_g, xb.x, bias0_g), 0.f);
                u64 a5 = packf2(fmaf(wx_g, xb.y, bias0_g), 0.f);
                u64 a6 = packf2(fmaf(wx_g, xb.z, bias0_g), 0.f);
                u64 a7 = packf2(fmaf(wx_g, xb.w, bias0_g), 0.f);
                #pragma unroll
                for (int jj = 0; jj < 32; ++jj) {
                    const ulonglong2* hp = (const ulonglong2*)&hbase[jj * 16];
                    u64 w0 = w0p[jj];
                    ulonglong2 h01 = hp[0];
                    ffma2(a0, w0, h01.x); ffma2(a1, w0, h01.y);
                    ulonglong2 h23 = hp[1];
                    ffma2(a2, w0, h23.x); ffma2(a3, w0, h23.y);
                    ulonglong2 h45 = hp[2];
                    ffma2(a4, w0, h45.x); ffma2(a5, w0, h45.y);
                    ulonglong2 h67 = hp[3];
                    ffma2(a6, w0, h67.x); ffma2(a7, w0, h67.y);
                }
                float2 p0 = unpackf2(a0), p1 = unpackf2(a1), p2 = unpackf2(a2), p3 = unpackf2(a3);
                float2 p4 = unpackf2(a4), p5 = unpackf2(a5), p6 = unpackf2(a6), p7 = unpackf2(a7);
                float4* gp = (float4*)&sm[SGT0 + g * 8];
                gp[0] = make_float4(p0.x + p0.y, p1.x + p1.y, p2.x + p2.y, p3.x + p3.y);
                gp[1] = make_float4(p4.x + p4.y, p5.x + p5.y, p6.x + p6.y, p7.x + p7.y);
            }
            asm volatile("bar.sync 1, 256;" ::: "memory");   // A-group gates ready
            if (s < 512) {
                {
                    float iv = sm[SGT0 + (j0)       * 8 + bb];
                    float fv = sm[SGT0 + (64 + j0)  * 8 + bb];
                    float gv = sm[SGT0 + (128 + j0) * 8 + bb];
                    float ov = sm[SGT0 + (192 + j0) * 8 + bb];
                    c0a = fsig(fv) * c0a + fsig(iv) * ftanh(gv);
                    hdst[hs1a] = fsig(ov) * ftanh(c0a);
                }
                {
                    float iv = sm[SGT0 + (jB)       * 8 + bb];
                    float fv = sm[SGT0 + (64 + jB)  * 8 + bb];
                    float gv = sm[SGT0 + (128 + jB) * 8 + bb];
                    float ov = sm[SGT0 + (192 + jB) * 8 + bb];
                    c0b = fsig(fv) * c0b + fsig(iv) * ftanh(gv);
                    hdst[hs1b] = fsig(ov) * ftanh(c0b);
                }
            }
            asm volatile("bar.sync 0, 512;" ::: "memory");   // publish h
        }
    } else {
        // =============== GROUP B: layer-1 gates + layer-1 update ===============
        u64 w1p[32];                                     // Wih1 row g (multiplies h1_t)
        {
            const u64* pi = (const u64*)(Wih1 + g * 64);
            #pragma unroll
            for (int q = 0; q < 32; ++q) w1p[q] = pi[q];
        }
        const u64 init1 = packf2(bih1[g] + bhh1[g], 0.f);
        float c1a = 0.f, c1b = 0.f;

        for (int s = 0; s <= 512; ++s) {
            const float* hbase = &sm[SHC + (s & 1) * 1024];
            float*       hdst  = &sm[SHC + ((s + 1) & 1) * 1024];
            if (s > 0) {
                u64 q0 = init1, q1 = init1, q2 = init1, q3 = init1;
                u64 q4 = init1, q5 = init1, q6 = init1, q7 = init1;
                // h1 half (weights in registers)
                #pragma unroll
                for (int jj = 0; jj < 32; ++jj) {
                    const ulonglong2* hp = (const ulonglong2*)&hbase[jj * 16];
                    u64 w1 = w1p[jj];
                    ulonglong2 h01 = hp[0];
                    ffma2(q0, w1, h01.x); ffma2(q1, w1, h01.y);
                    ulonglong2 h23 = hp[1];
                    ffma2(q2, w1, h23.x); ffma2(q3, w1, h23.y);
                    ulonglong2 h45 = hp[2];
                    ffma2(q4, w1, h45.x); ffma2(q5, w1, h45.y);
                    ulonglong2 h67 = hp[3];
                    ffma2(q6, w1, h67.x); ffma2(q7, w1, h67.y);
                }
                // h2 half (weights from tid-indexed smem, conflict-free LDS.64)
                #pragma unroll
                for (int jj = 0; jj < 32; ++jj) {
                    const ulonglong2* hp = (const ulonglong2*)&hbase[512 + jj * 16];
                    u64 w2 = smW[jj * 256 + g];
                    ulonglong2 h01 = hp[0];
                    ffma2(q0, w2, h01.x); ffma2(q1, w2, h01.y);
                    ulonglong2 h23 = hp[1];
                    ffma2(q2, w2, h23.x); ffma2(q3, w2, h23.y);
                    ulonglong2 h45 = hp[2];
                    ffma2(q4, w2, h45.x); ffma2(q5, w2, h45.y);
                    ulonglong2 h67 = hp[3];
                    ffma2(q6, w2, h67.x); ffma2(q7, w2, h67.y);
                }
                float2 p0 = unpackf2(q0), p1 = unpackf2(q1), p2 = unpackf2(q2), p3 = unpackf2(q3);
                float2 p4 = unpackf2(q4), p5 = unpackf2(q5), p6 = unpackf2(q6), p7 = unpackf2(q7);
                float4* gp = (float4*)&sm[SGT1 + g * 8];
                gp[0] = make_float4(p0.x + p0.y, p1.x + p1.y, p2.x + p2.y, p3.x + p3.y);
                gp[1] = make_float4(p4.x + p4.y, p5.x + p5.y, p6.x + p6.y, p7.x + p7.y);
            }
            asm volatile("bar.sync 2, 256;" ::: "memory");   // B-group gates ready
            if (s > 0) {
                {
                    float iv = sm[SGT1 + (j0)       * 8 + bb];
                    float fv = sm[SGT1 + (64 + j0)  * 8 + bb];
                    float gv = sm[SGT1 + (128 + j0) * 8 + bb];
                    float ov = sm[SGT1 + (192 + j0) * 8 + bb];
                    c1a = fsig(fv) * c1a + fsig(iv) * ftanh(gv);
                    hdst[hs2a] = fsig(ov) * ftanh(c1a);
                }
                {
                    float iv = sm[SGT1 + (jB)       * 8 + bb];
                    float fv = sm[SGT1 + (64 + jB)  * 8 + bb];
                    float gv = sm[SGT1 + (128 + jB) * 8 + bb];
                    float ov = sm[SGT1 + (192 + jB) * 8 + bb];
                    c1b = fsig(fv) * c1b + fsig(iv) * ftanh(gv);
                    hdst[hs2b] = fsig(ov) * ftanh(c1b);
                }
            }
            asm volatile("bar.sync 0, 512;" ::: "memory");   // publish h
        }
    }
    __syncthreads();

    // ===== Final FC on h2[T-1]: O=1 =====
    // Last h2 write was iter s=512 into buf[(512+1)&1] = buf 1.
    if (tid < 8) {
        float acc = bfc[0];
        #pragma unroll 8
        for (int k = 64; k < 128; ++k)
            acc = fmaf(Wfc[k - 64],
                       sm[SHC + 1024 + (k >> 1) * 16 + tid * 2 + (k & 1)], acc);
        out[b0 + tid] = acc;
    }
}

extern "C" void kernel_launch(void* const* d_in, const int* in_sizes, int n_in,
                              void* d_out, int out_size)
{
    const float* x    = (const float*)d_in[0];
    const float* Wih0 = (const float*)d_in[1];
    const float* Whh0 = (const float*)d_in[2];
    const float* bih0 = (const float*)d_in[3];
    const float* bhh0 = (const float*)d_in[4];
    const float* Wih1 = (const float*)d_in[5];
    const float* Whh1 = (const float*)d_in[6];
    const float* bih1 = (const float*)d_in[7];
    const float* bhh1 = (const float*)d_in[8];
    const float* Wfc  = (const float*)d_in[9];
    const float* bfc  = (const float*)d_in[10];
    float* out = (float*)d_out;

    cudaFuncSetAttribute(lstm2_kernel,
                         cudaFuncAttributeMaxDynamicSharedMemorySize,
                         SMEM_FLOATS * sizeof(float));
    lstm2_kernel<<<128, 512, SMEM_FLOATS * sizeof(float)>>>(
        x, Wih0, Whh0, bih0, bhh0, Wih1, Whh1, bih1, bhh1, Wfc, bfc, out);
}